// round 1
// baseline (speedup 1.0000x reference)
#include <cuda_runtime.h>
#include <math.h>

#define BATCH 128
#define NDIM 512
#define POWER_ITERS 30
#define N_ITERS 500
#define NTHREADS 512
#define NWARPS 16

// 512 MB scratch for the symmetrized Sigma (allowed: __device__ global array)
__device__ float g_Ssym[(size_t)BATCH * NDIM * NDIM];

// ---------------------------------------------------------------------------
// Kernel 1: Sigma_sym = 0.5 * (Sigma + Sigma^T), tiled for coalescing
// ---------------------------------------------------------------------------
__global__ void symmetrize_kernel(const float* __restrict__ Sigma) {
    __shared__ float tA[32][33];
    __shared__ float tB[32][33];
    const int b  = blockIdx.z;
    const int ti = blockIdx.y * 32;   // row tile base
    const int tj = blockIdx.x * 32;   // col tile base
    const float* S = Sigma + (size_t)b * NDIM * NDIM;
    float* O = g_Ssym + (size_t)b * NDIM * NDIM;
    const int tx = threadIdx.x, ty = threadIdx.y;

    #pragma unroll
    for (int r = ty; r < 32; r += 8) {
        tA[r][tx] = S[(size_t)(ti + r) * NDIM + (tj + tx)];
        tB[r][tx] = S[(size_t)(tj + r) * NDIM + (ti + tx)];
    }
    __syncthreads();
    #pragma unroll
    for (int r = ty; r < 32; r += 8) {
        O[(size_t)(ti + r) * NDIM + (tj + tx)] = 0.5f * (tA[r][tx] + tB[tx][r]);
    }
}

// ---------------------------------------------------------------------------
// Block reductions (512 threads, 16 warps). Two barriers per call.
// All threads receive the result (deterministic shuffle order).
// ---------------------------------------------------------------------------
__device__ __forceinline__ float block_sum(float v, volatile float* red,
                                           int lane, int wid) {
    #pragma unroll
    for (int o = 16; o; o >>= 1) v += __shfl_xor_sync(0xffffffffu, v, o);
    __syncthreads();                       // protect red from previous use
    if (lane == 0) red[wid] = v;
    __syncthreads();
    float x = (lane < NWARPS) ? red[lane] : 0.0f;
    #pragma unroll
    for (int o = 16; o; o >>= 1) x += __shfl_xor_sync(0xffffffffu, x, o);
    return x;
}

__device__ __forceinline__ float2 block_sum2(float a, float b, volatile float* red,
                                             int lane, int wid) {
    #pragma unroll
    for (int o = 16; o; o >>= 1) {
        a += __shfl_xor_sync(0xffffffffu, a, o);
        b += __shfl_xor_sync(0xffffffffu, b, o);
    }
    __syncthreads();
    if (lane == 0) { red[wid] = a; red[NWARPS + wid] = b; }
    __syncthreads();
    float xa = (lane < NWARPS) ? red[lane] : 0.0f;
    float xb = (lane < NWARPS) ? red[NWARPS + lane] : 0.0f;
    #pragma unroll
    for (int o = 16; o; o >>= 1) {
        xa += __shfl_xor_sync(0xffffffffu, xa, o);
        xb += __shfl_xor_sync(0xffffffffu, xb, o);
    }
    return make_float2(xa, xb);
}

// ---------------------------------------------------------------------------
// out = S * y   (S: 512x512 row-major fp32, y in SMEM, out in SMEM)
// Each warp owns 32 rows; 8 lanes per row, float4 loads (fully coalesced),
// 3-shuffle in-group reduce. Caller must __syncthreads() after.
// ---------------------------------------------------------------------------
__device__ __forceinline__ void matvec512(const float* __restrict__ S,
                                          const float* __restrict__ yv,
                                          float* __restrict__ outv,
                                          int lane, int wid) {
    const int g = lane >> 3;   // row within group of 4
    const int l = lane & 7;    // lane within 8-lane row team
    const float4* Y4 = (const float4*)yv;
    #pragma unroll 2
    for (int p = 0; p < 8; ++p) {
        const int row = (wid << 5) + (p << 2) + g;
        const float4* R = (const float4*)(S + ((size_t)row << 9));
        float acc = 0.0f;
        #pragma unroll
        for (int k = 0; k < 16; ++k) {
            float4 a = R[l + (k << 3)];
            float4 b = Y4[l + (k << 3)];
            acc += a.x * b.x + a.y * b.y + a.z * b.z + a.w * b.w;
        }
        acc += __shfl_xor_sync(0xffffffffu, acc, 1);
        acc += __shfl_xor_sync(0xffffffffu, acc, 2);
        acc += __shfl_xor_sync(0xffffffffu, acc, 4);
        if (l == 0) outv[row] = acc;
    }
}

// ---------------------------------------------------------------------------
// Kernel 2: per-instance solver. grid = 128 CTAs, block = 512 threads.
// Power iteration (30) -> lmax -> step -> FISTA (500) with simplex projection.
// ---------------------------------------------------------------------------
__global__ void __launch_bounds__(NTHREADS, 1)
qp_solver_kernel(const float* __restrict__ mu_g, float* __restrict__ out) {
    __shared__ float sh_y[NDIM];
    __shared__ float sh_w[NDIM];
    __shared__ float sh_mu[NDIM];
    __shared__ float sh_g[NDIM];
    __shared__ float red[2 * NWARPS];

    const int b    = blockIdx.x;
    const int tid  = threadIdx.x;
    const int lane = tid & 31;
    const int wid  = tid >> 5;
    const float* S = g_Ssym + (size_t)b * NDIM * NDIM;
    const float invN = 1.0f / (float)NDIM;

    sh_mu[tid] = mu_g[(size_t)b * NDIM + tid];
    sh_y[tid]  = invN;                        // power-iteration b0
    __syncthreads();

    // ---- power iteration: lambda_max estimate ----
    for (int it = 0; it < POWER_ITERS; ++it) {
        matvec512(S, sh_y, sh_g, lane, wid);
        __syncthreads();
        float gi = sh_g[tid];
        float ss = block_sum(gi * gi, red, lane, wid);
        float inv = 1.0f / (sqrtf(ss) + 1e-12f);
        sh_y[tid] = gi * inv;                 // safe: block_sum barrier passed
        __syncthreads();
    }
    matvec512(S, sh_y, sh_g, lane, wid);
    __syncthreads();
    const float lmax = block_sum(sh_y[tid] * sh_g[tid], red, lane, wid);
    const float step = 1.0f / (2.0f * lmax + 1e-8f);

    // ---- FISTA ----
    sh_w[tid] = invN;
    sh_y[tid] = invN;
    __syncthreads();
    float t = 1.0f;

    for (int it = 0; it < N_ITERS; ++it) {
        matvec512(S, sh_y, sh_g, lane, wid);
        __syncthreads();
        const float v = sh_y[tid] - step * (2.0f * sh_g[tid] - sh_mu[tid]);

        // Euclidean projection onto the simplex (Michelot fixed point:
        // theta s.t. active = {v > theta}, theta = (sum_active - 1)/|active|,
        // identical to the reference's sort/cumsum construction)
        float s0 = block_sum(v, red, lane, wid);
        float theta = (s0 - 1.0f) * invN;
        for (int pit = 0; pit < 64; ++pit) {
            const bool act = (v > theta);
            float2 sk = block_sum2(act ? v : 0.0f, act ? 1.0f : 0.0f,
                                   red, lane, wid);
            const float tn = (sk.x - 1.0f) / sk.y;
            if (tn == theta) break;           // uniform across block
            theta = tn;
        }
        const float wn   = fmaxf(v - theta, 0.0f);
        const float wold = sh_w[tid];
        const float tnew = 0.5f * (1.0f + sqrtf(1.0f + 4.0f * t * t));
        const float yn   = wn + ((t - 1.0f) / tnew) * (wn - wold);
        t = tnew;
        __syncthreads();                      // everyone done reading sh_w/sh_y
        sh_w[tid] = wn;
        sh_y[tid] = yn;
        __syncthreads();
    }

    out[(size_t)b * NDIM + tid] = sh_w[tid];
}

// ---------------------------------------------------------------------------
extern "C" void kernel_launch(void* const* d_in, const int* in_sizes, int n_in,
                              void* d_out, int out_size) {
    const float* mu    = (const float*)d_in[0];   // [128, 512]
    const float* Sigma = (const float*)d_in[1];   // [128, 512, 512]
    float* out = (float*)d_out;                   // [128, 512] fp32

    dim3 gs(NDIM / 32, NDIM / 32, BATCH);
    dim3 bs(32, 8);
    symmetrize_kernel<<<gs, bs>>>(Sigma);
    qp_solver_kernel<<<BATCH, NTHREADS>>>(mu, out);
}

// round 3
// speedup vs baseline: 7.5266x; 7.5266x over previous
#include <cuda_runtime.h>
#include <math.h>

#define BATCH 128
#define NDIM 512
#define POWER_ITERS 30
#define N_ITERS 500
#define NTHREADS 512
#define NWARPS 16
#define NTILES 136              // 16*17/2 upper-triangular 32x32 tiles
#define TILE_ELEMS 1024
#define INST_STRIDE (NTILES * TILE_ELEMS)   // floats per instance (544 KB)

// Packed symmetric Sigma: 128 * 544KB = 68 MB (L2-resident)
__device__ float g_pack[(size_t)BATCH * INST_STRIDE];

// ---------------------------------------------------------------------------
// Kernel 1: symmetrize + pack upper triangle into tile layout.
//  off-diag tile (I<J):  P[d*32+i] = T[(i+d)&31][i]   (diag-shifted, coalesced)
//  diag tile (I==J):     P[c*32+r] = T[r][c]          (column-major)
//  where T = 0.5*(Sigma_IJ + Sigma_JI^T)
// ---------------------------------------------------------------------------
__global__ void pack_kernel(const float* __restrict__ Sigma) {
    __shared__ float sA[32][33];
    __shared__ float sB[32][33];
    const int t = blockIdx.x;
    const int b = blockIdx.y;
    // map linear tile index -> (I, J), I<=J
    int I = 0, rem = t;
    while (rem >= 16 - I) { rem -= 16 - I; ++I; }
    const int J = I + rem;

    const float* S = Sigma + (size_t)b * NDIM * NDIM;
    float* P = g_pack + (size_t)b * INST_STRIDE + (size_t)t * TILE_ELEMS;
    const int tx = threadIdx.x, ty = threadIdx.y;

    #pragma unroll
    for (int r = ty; r < 32; r += 8) {
        sA[r][tx] = S[(size_t)(I * 32 + r) * NDIM + J * 32 + tx]; // Sigma[Ib+r][Jb+c]
        sB[r][tx] = S[(size_t)(J * 32 + r) * NDIM + I * 32 + tx]; // Sigma[Jb+r][Ib+c]
    }
    __syncthreads();

    if (I == J) {
        #pragma unroll
        for (int c = ty; c < 32; c += 8)            // T[r][c], r = tx
            P[c * 32 + tx] = 0.5f * (sA[tx][c] + sB[c][tx]);
    } else {
        #pragma unroll
        for (int d = ty; d < 32; d += 8) {
            const int r = (tx + d) & 31;            // i = tx
            P[d * 32 + tx] = 0.5f * (sA[r][tx] + sB[tx][r]);
        }
    }
}

// ---------------------------------------------------------------------------
// Block reductions (512 threads / 16 warps), deterministic order.
// ---------------------------------------------------------------------------
__device__ __forceinline__ float block_sum(float v, volatile float* red,
                                           int lane, int wid) {
    #pragma unroll
    for (int o = 16; o; o >>= 1) v += __shfl_xor_sync(0xffffffffu, v, o);
    __syncthreads();
    if (lane == 0) red[wid] = v;
    __syncthreads();
    float x = (lane < NWARPS) ? red[lane] : 0.0f;
    #pragma unroll
    for (int o = 16; o; o >>= 1) x += __shfl_xor_sync(0xffffffffu, x, o);
    return x;
}

__device__ __forceinline__ float2 block_sum2(float a, float b, volatile float* red,
                                             int lane, int wid) {
    #pragma unroll
    for (int o = 16; o; o >>= 1) {
        a += __shfl_xor_sync(0xffffffffu, a, o);
        b += __shfl_xor_sync(0xffffffffu, b, o);
    }
    __syncthreads();
    if (lane == 0) { red[wid] = a; red[NWARPS + wid] = b; }
    __syncthreads();
    float xa = (lane < NWARPS) ? red[lane] : 0.0f;
    float xb = (lane < NWARPS) ? red[NWARPS + lane] : 0.0f;
    #pragma unroll
    for (int o = 16; o; o >>= 1) {
        xa += __shfl_xor_sync(0xffffffffu, xa, o);
        xb += __shfl_xor_sync(0xffffffffu, xb, o);
    }
    return make_float2(xa, xb);
}

__device__ __forceinline__ float block_max(float v, volatile float* red,
                                           int lane, int wid) {
    #pragma unroll
    for (int o = 16; o; o >>= 1) v = fmaxf(v, __shfl_xor_sync(0xffffffffu, v, o));
    __syncthreads();
    if (lane == 0) red[wid] = v;
    __syncthreads();
    float x = (lane < NWARPS) ? red[lane] : 0.0f;
    #pragma unroll
    for (int o = 16; o; o >>= 1) x = fmaxf(x, __shfl_xor_sync(0xffffffffu, x, o));
    return x;
}

// ---------------------------------------------------------------------------
// Symmetric matvec from packed tiles. Each element of Sigma's upper triangle
// is loaded ONCE and contributes to both out_I and out_J.
// Per-warp private accumulators (deterministic), reduced across warps at end.
// Returns (Ssym * y)[tid]. Leaves block at a barrier-consistent point.
// ---------------------------------------------------------------------------
__device__ __forceinline__ float matvec_sym(const float* __restrict__ P,
                                            const float* __restrict__ yv,
                                            float* __restrict__ accAll,
                                            const int* __restrict__ tI,
                                            const int* __restrict__ tJ,
                                            int tid, int lane, int wid) {
    float* acc = accAll + (wid << 9);
    #pragma unroll
    for (int k = lane; k < NDIM; k += 32) acc[k] = 0.0f;  // own lanes only

    for (int t = wid; t < NTILES; t += NWARPS) {
        const float* PT = P + t * TILE_ELEMS;
        const int I = tI[t], J = tJ[t];
        const float* yI = yv + I * 32;
        if (I == J) {
            float a = 0.0f;
            #pragma unroll
            for (int c = 0; c < 32; ++c)
                a = fmaf(PT[c * 32 + lane], yI[c], a);    // LDS broadcast on yI[c]
            acc[I * 32 + lane] += a;
        } else {
            const float ryJ = yv[J * 32 + lane];
            float arow = 0.0f, acol = 0.0f;
            #pragma unroll
            for (int d = 0; d < 32; ++d) {
                const float e = PT[d * 32 + lane];        // T[(lane+d)&31][lane]
                acol = fmaf(e, yI[(lane + d) & 31], acol);
                const float tt = e * ryJ;
                arow += __shfl_sync(0xffffffffu, tt, (lane - d) & 31);
            }
            acc[I * 32 + lane] += arow;
            acc[J * 32 + lane] += acol;
        }
    }
    __syncthreads();
    float s = 0.0f;
    #pragma unroll
    for (int w = 0; w < NWARPS; ++w) s += accAll[(w << 9) + tid];
    return s;
}

// ---------------------------------------------------------------------------
// Kernel 2: per-instance solver. grid=128 CTAs, block=512 threads.
// ---------------------------------------------------------------------------
__global__ void __launch_bounds__(NTHREADS, 1)
qp_solver_kernel(const float* __restrict__ mu_g, float* __restrict__ out) {
    __shared__ float sh_acc[NWARPS * NDIM];   // 32 KB per-warp accumulators
    __shared__ float sh_y[NDIM];
    __shared__ float red[2 * NWARPS];
    __shared__ int   sh_tI[NTILES], sh_tJ[NTILES];

    const int b    = blockIdx.x;
    const int tid  = threadIdx.x;
    const int lane = tid & 31;
    const int wid  = tid >> 5;
    const float* P = g_pack + (size_t)b * INST_STRIDE;
    const float invN = 1.0f / (float)NDIM;

    if (tid < NTILES) {                       // tile index tables
        int I = 0, rem = tid;
        while (rem >= 16 - I) { rem -= 16 - I; ++I; }
        sh_tI[tid] = I;
        sh_tJ[tid] = I + rem;
    }
    const float rmu = mu_g[(size_t)b * NDIM + tid];
    sh_y[tid] = invN;
    __syncthreads();

    // ---- power iteration ----
    float ry = invN;
    for (int it = 0; it < POWER_ITERS; ++it) {
        const float gi = matvec_sym(P, sh_y, sh_acc, sh_tI, sh_tJ, tid, lane, wid);
        const float ss = block_sum(gi * gi, red, lane, wid);
        const float inv = 1.0f / (sqrtf(ss) + 1e-12f);
        ry = gi * inv;
        sh_y[tid] = ry;                       // safe: block_sum barriers passed
        __syncthreads();
    }
    {
        const float gi = matvec_sym(P, sh_y, sh_acc, sh_tI, sh_tJ, tid, lane, wid);
        const float lmax = block_sum(ry * gi, red, lane, wid);
        const float step = 1.0f / (2.0f * lmax + 1e-8f);

        // ---- FISTA ----
        float rw = invN, t = 1.0f;
        ry = invN;
        __syncthreads();                      // all past reads of sh_y done
        sh_y[tid] = invN;
        __syncthreads();

        for (int it = 0; it < N_ITERS; ++it) {
            const float gi2 = matvec_sym(P, sh_y, sh_acc, sh_tI, sh_tJ, tid, lane, wid);
            const float v = ry - step * (2.0f * gi2 - rmu);

            // simplex projection: Michelot fixed point (== sort-based theta)
            float s0 = block_sum(v, red, lane, wid);
            float theta = (s0 - 1.0f) * invN;
            for (int pit = 0; pit < 64; ++pit) {
                const bool act = (v > theta);
                float2 sk = block_sum2(act ? v : 0.0f, act ? 1.0f : 0.0f,
                                       red, lane, wid);
                const float tn = (sk.x - 1.0f) / sk.y;
                if (tn == theta) break;       // uniform
                theta = tn;
            }
            const float wn   = fmaxf(v - theta, 0.0f);
            const float diff = fabsf(wn - rw);
            const float tnew = 0.5f * (1.0f + sqrtf(1.0f + 4.0f * t * t));
            const float yn   = wn + ((t - 1.0f) / tnew) * (wn - rw);
            t = tnew; rw = wn; ry = yn;

            const float mx = block_max(diff, red, lane, wid);
            sh_y[tid] = yn;                   // safe: block_max barriers passed
            if (mx < 1e-7f) break;            // converged: rest is fp dither
            __syncthreads();
        }
        out[(size_t)b * NDIM + tid] = rw;
    }
}

// ---------------------------------------------------------------------------
extern "C" void kernel_launch(void* const* d_in, const int* in_sizes, int n_in,
                              void* d_out, int out_size) {
    const float* mu    = (const float*)d_in[0];   // [128, 512]
    const float* Sigma = (const float*)d_in[1];   // [128, 512, 512]
    float* out = (float*)d_out;                   // [128, 512]

    dim3 gs(NTILES, BATCH);
    dim3 bs(32, 8);
    pack_kernel<<<gs, bs>>>(Sigma);
    qp_solver_kernel<<<BATCH, NTHREADS>>>(mu, out);
}

// round 4
// speedup vs baseline: 16.0874x; 2.1374x over previous
#include <cuda_runtime.h>
#include <math.h>

#define BATCH 128
#define NDIM 512
#define POWER_ITERS 16
#define N_ITERS 500
#define NTHREADS 512
#define NWARPS 16
#define NTILES 136              // 16*17/2 upper-triangular 32x32 tiles
#define TILE_ELEMS 1024
#define INST_STRIDE (NTILES * TILE_ELEMS)   // floats per instance (544 KB)

// dynamic smem layout (floats)
#define ACC_OFF   0                         // 16 x 512
#define STAGE_OFF 8192                      // 16 x (32*36)
#define SY_OFF    (8192 + 16 * 1152)        // 512
#define DSM_FLOATS (SY_OFF + 512)
#define DSM_BYTES (DSM_FLOATS * 4)          // 108544 B

// Packed symmetric Sigma: 128 * 544KB = 68 MB (L2-resident)
__device__ float g_pack[(size_t)BATCH * INST_STRIDE];

// ---------------------------------------------------------------------------
// Kernel 1: symmetrize + pack upper triangle.
// Within-tile layout: P[k*128 + c*4 + j] = T[4k+j][c],  T = 0.5(S_IJ + S_JI^T)
// (float4 over the row index j for pass-A vector loads)
// ---------------------------------------------------------------------------
__global__ void pack_kernel(const float* __restrict__ Sigma) {
    __shared__ float sA[32][33];
    __shared__ float sB[32][33];
    const int t = blockIdx.x;
    const int b = blockIdx.y;
    int I = 0, rem = t;
    while (rem >= 16 - I) { rem -= 16 - I; ++I; }
    const int J = I + rem;

    const float* S = Sigma + (size_t)b * NDIM * NDIM;
    float* P = g_pack + (size_t)b * INST_STRIDE + (size_t)t * TILE_ELEMS;
    const int tx = threadIdx.x, ty = threadIdx.y;
    const int tid = ty * 32 + tx;

    #pragma unroll
    for (int r = ty; r < 32; r += 8) {
        sA[r][tx] = S[(size_t)(I * 32 + r) * NDIM + J * 32 + tx]; // S[Ib+r][Jb+c]
        sB[r][tx] = S[(size_t)(J * 32 + r) * NDIM + I * 32 + tx]; // S[Jb+r][Ib+c]
    }
    __syncthreads();

    #pragma unroll
    for (int q = 0; q < 4; ++q) {
        const int addr = tid + (q << 8);
        const int k = addr >> 7;
        const int c = (addr >> 2) & 31;
        const int j = addr & 3;
        const int r = (k << 2) + j;
        P[addr] = 0.5f * (sA[r][c] + sB[c][r]);   // T[r][c]
    }
}

// ---------------------------------------------------------------------------
// Block reductions (512 threads / 16 warps), deterministic order.
// ---------------------------------------------------------------------------
__device__ __forceinline__ float block_sum(float v, volatile float* red,
                                           int lane, int wid) {
    #pragma unroll
    for (int o = 16; o; o >>= 1) v += __shfl_xor_sync(0xffffffffu, v, o);
    __syncthreads();
    if (lane == 0) red[wid] = v;
    __syncthreads();
    float x = (lane < NWARPS) ? red[lane] : 0.0f;
    #pragma unroll
    for (int o = 16; o; o >>= 1) x += __shfl_xor_sync(0xffffffffu, x, o);
    return x;
}

__device__ __forceinline__ float2 block_sum2(float a, float b, volatile float* red,
                                             int lane, int wid) {
    #pragma unroll
    for (int o = 16; o; o >>= 1) {
        a += __shfl_xor_sync(0xffffffffu, a, o);
        b += __shfl_xor_sync(0xffffffffu, b, o);
    }
    __syncthreads();
    if (lane == 0) { red[wid] = a; red[NWARPS + wid] = b; }
    __syncthreads();
    float xa = (lane < NWARPS) ? red[lane] : 0.0f;
    float xb = (lane < NWARPS) ? red[NWARPS + lane] : 0.0f;
    #pragma unroll
    for (int o = 16; o; o >>= 1) {
        xa += __shfl_xor_sync(0xffffffffu, xa, o);
        xb += __shfl_xor_sync(0xffffffffu, xb, o);
    }
    return make_float2(xa, xb);
}

// max of a, sum of b
__device__ __forceinline__ float2 block_max_sum(float a, float b, volatile float* red,
                                                int lane, int wid) {
    #pragma unroll
    for (int o = 16; o; o >>= 1) {
        a = fmaxf(a, __shfl_xor_sync(0xffffffffu, a, o));
        b += __shfl_xor_sync(0xffffffffu, b, o);
    }
    __syncthreads();
    if (lane == 0) { red[wid] = a; red[NWARPS + wid] = b; }
    __syncthreads();
    float xa = (lane < NWARPS) ? red[lane] : -1e30f;
    float xb = (lane < NWARPS) ? red[NWARPS + lane] : 0.0f;
    #pragma unroll
    for (int o = 16; o; o >>= 1) {
        xa = fmaxf(xa, __shfl_xor_sync(0xffffffffu, xa, o));
        xb += __shfl_xor_sync(0xffffffffu, xb, o);
    }
    return make_float2(xa, xb);
}

// ---------------------------------------------------------------------------
// Symmetric matvec, staged two-pass per tile (no shuffles).
//  pass A (lane = c): acol[c] = sum_r T[r][c] * yI[r]  -> block J
//                     + stage tile rows into SMEM stg[r*36 + c]
//  pass B (lane = r): brow[r] = sum_c T[r][c] * yJ[c]  -> block I
// Returns (Ssym * y)[tid].
// ---------------------------------------------------------------------------
__device__ __forceinline__ float matvec_sym(const float* __restrict__ P,
                                            const float* __restrict__ sy,
                                            float* __restrict__ accAll,
                                            float* __restrict__ stageAll,
                                            const int* __restrict__ tI,
                                            const int* __restrict__ tJ,
                                            int tid, int lane, int wid) {
    float* acc = accAll + (wid << 9);
    {   // zero own 512-float accumulator: 4 x STS.128 per lane
        const float4 z = make_float4(0.f, 0.f, 0.f, 0.f);
        float4* a4 = (float4*)acc;
        a4[lane] = z; a4[lane + 32] = z; a4[lane + 64] = z; a4[lane + 96] = z;
    }
    float* stg = stageAll + wid * 1152;

    for (int t = wid; t < NTILES; t += NWARPS) {
        const float4* PT4 = (const float4*)(P + t * TILE_ELEMS);
        const int I = tI[t], J = tJ[t];
        const float4* yI4 = (const float4*)(sy + (I << 5));
        float a0 = 0.f, a1 = 0.f;
        if (I == J) {
            #pragma unroll
            for (int k = 0; k < 8; ++k) {
                const float4 e  = PT4[(k << 5) + lane];
                const float4 yb = yI4[k];                     // broadcast
                a0 = fmaf(e.x, yb.x, a0); a1 = fmaf(e.y, yb.y, a1);
                a0 = fmaf(e.z, yb.z, a0); a1 = fmaf(e.w, yb.w, a1);
            }
            acc[(J << 5) + lane] += a0 + a1;
        } else {
            #pragma unroll
            for (int k = 0; k < 8; ++k) {
                const float4 e  = PT4[(k << 5) + lane];
                const float4 yb = yI4[k];
                a0 = fmaf(e.x, yb.x, a0); a1 = fmaf(e.y, yb.y, a1);
                a0 = fmaf(e.z, yb.z, a0); a1 = fmaf(e.w, yb.w, a1);
                stg[((k << 2) + 0) * 36 + lane] = e.x;        // conflict-free
                stg[((k << 2) + 1) * 36 + lane] = e.y;
                stg[((k << 2) + 2) * 36 + lane] = e.z;
                stg[((k << 2) + 3) * 36 + lane] = e.w;
            }
            acc[(J << 5) + lane] += a0 + a1;
            __syncwarp();                                     // STS -> cross-lane LDS
            const float4* yJ4 = (const float4*)(sy + (J << 5));
            float b0 = 0.f, b1 = 0.f;
            #pragma unroll
            for (int m = 0; m < 8; ++m) {
                const float4 s  = *(const float4*)(stg + lane * 36 + (m << 2));
                const float4 yb = yJ4[m];                     // broadcast
                b0 = fmaf(s.x, yb.x, b0); b1 = fmaf(s.y, yb.y, b1);
                b0 = fmaf(s.z, yb.z, b0); b1 = fmaf(s.w, yb.w, b1);
            }
            acc[(I << 5) + lane] += b0 + b1;
            __syncwarp();                                     // before stg reuse
        }
    }
    __syncthreads();
    float s = 0.0f;
    #pragma unroll
    for (int w = 0; w < NWARPS; ++w) s += accAll[(w << 9) + tid];
    return s;
}

// ---------------------------------------------------------------------------
// Kernel 2: per-instance solver. grid=128 CTAs, block=512 threads.
// Power iteration -> step; FISTA + adaptive restart + early exit.
// ---------------------------------------------------------------------------
__global__ void __launch_bounds__(NTHREADS, 1)
qp_solver_kernel(const float* __restrict__ mu_g, float* __restrict__ out) {
    extern __shared__ float dsm[];
    float* accAll   = dsm + ACC_OFF;
    float* stageAll = dsm + STAGE_OFF;
    float* sy       = dsm + SY_OFF;
    __shared__ float red[2 * NWARPS];
    __shared__ int   sh_tI[NTILES], sh_tJ[NTILES];

    const int b    = blockIdx.x;
    const int tid  = threadIdx.x;
    const int lane = tid & 31;
    const int wid  = tid >> 5;
    const float* P = g_pack + (size_t)b * INST_STRIDE;
    const float invN = 1.0f / (float)NDIM;

    if (tid < NTILES) {
        int I = 0, rem = tid;
        while (rem >= 16 - I) { rem -= 16 - I; ++I; }
        sh_tI[tid] = I;
        sh_tJ[tid] = I + rem;
    }
    const float rmu = mu_g[(size_t)b * NDIM + tid];
    sy[tid] = invN;
    __syncthreads();

    // ---- power iteration (answer is step-independent; margin below) ----
    float ry = invN;
    for (int it = 0; it < POWER_ITERS; ++it) {
        const float gi = matvec_sym(P, sy, accAll, stageAll, sh_tI, sh_tJ, tid, lane, wid);
        const float ss = block_sum(gi * gi, red, lane, wid);
        const float inv = 1.0f / (sqrtf(ss) + 1e-12f);
        ry = gi * inv;
        sy[tid] = ry;                         // safe: block_sum barriers passed
        __syncthreads();
    }
    const float gi0  = matvec_sym(P, sy, accAll, stageAll, sh_tI, sh_tJ, tid, lane, wid);
    const float lmax = block_sum(ry * gi0, red, lane, wid);
    const float step = 1.0f / (2.0f * lmax * 1.05f + 1e-8f);  // 5% safety margin

    // ---- FISTA with adaptive restart ----
    float rw = invN, t = 1.0f;
    ry = invN;
    __syncthreads();
    sy[tid] = invN;
    __syncthreads();

    for (int it = 0; it < N_ITERS; ++it) {
        const float gi = matvec_sym(P, sy, accAll, stageAll, sh_tI, sh_tJ, tid, lane, wid);
        const float v = ry - step * (2.0f * gi - rmu);

        // simplex projection (Michelot fixed point == sort-based theta)
        float s0 = block_sum(v, red, lane, wid);
        float theta = (s0 - 1.0f) * invN;
        for (int pit = 0; pit < 64; ++pit) {
            const bool act = (v > theta);
            float2 sk = block_sum2(act ? v : 0.0f, act ? 1.0f : 0.0f,
                                   red, lane, wid);
            const float tn = (sk.x - 1.0f) / sk.y;
            if (tn == theta) break;           // uniform across block
            theta = tn;
        }
        const float wn   = fmaxf(v - theta, 0.0f);
        const float diff = fabsf(wn - rw);
        const float rdot = (ry - wn) * (wn - rw);   // restart test term

        float2 ms = block_max_sum(diff, rdot, red, lane, wid);

        float yn;
        if (ms.y > 0.0f) {                    // restart (uniform)
            t = 1.0f;
            yn = wn;
        } else {
            const float tnew = 0.5f * (1.0f + sqrtf(1.0f + 4.0f * t * t));
            yn = wn + ((t - 1.0f) / tnew) * (wn - rw);
            t = tnew;
        }
        rw = wn; ry = yn;
        sy[tid] = yn;                         // safe: block_max_sum barriers passed
        if (ms.x < 1e-7f) break;              // converged (uniform)
        __syncthreads();
    }
    out[(size_t)b * NDIM + tid] = rw;
}

// ---------------------------------------------------------------------------
extern "C" void kernel_launch(void* const* d_in, const int* in_sizes, int n_in,
                              void* d_out, int out_size) {
    const float* mu    = (const float*)d_in[0];   // [128, 512]
    const float* Sigma = (const float*)d_in[1];   // [128, 512, 512]
    float* out = (float*)d_out;                   // [128, 512]

    cudaFuncSetAttribute(qp_solver_kernel,
                         cudaFuncAttributeMaxDynamicSharedMemorySize, DSM_BYTES);

    dim3 gs(NTILES, BATCH);
    dim3 bs(32, 8);
    pack_kernel<<<gs, bs>>>(Sigma);
    qp_solver_kernel<<<BATCH, NTHREADS, DSM_BYTES>>>(mu, out);
}

// round 5
// speedup vs baseline: 18.4493x; 1.1468x over previous
#include <cuda_runtime.h>
#include <math.h>

#define BATCH 128
#define NDIM 512
#define POWER_ITERS 16
#define N_ITERS 500
#define NTHREADS 512
#define NWARPS 16
#define NTILES 136              // 16*17/2 upper-triangular 32x32 tiles
#define TILE_ELEMS 1024
#define INST_STRIDE (NTILES * TILE_ELEMS)   // 544 KB per instance

// dynamic smem layout (floats)
#define ACC_OFF   0                          // 16 x 512
#define STAGE_OFF 8192                       // 16 x 1152 (32x36 per warp)
#define SY_OFF    (STAGE_OFF + 16 * 1152)
#define SV_OFF    (SY_OFF + NDIM)
#define SW_OFF    (SV_OFF + NDIM)
#define DSM_FLOATS (SW_OFF + NDIM)
#define DSM_BYTES (DSM_FLOATS * 4)

// Packed symmetric Sigma: 128 * 544KB = 68 MB (L2-resident)
__device__ float g_pack[(size_t)BATCH * INST_STRIDE];

// ---------------------------------------------------------------------------
// Kernel 1: symmetrize + pack upper triangle.
// Layout: P[k*128 + c*4 + j] = T[4k+j][c],  T = 0.5(S_IJ + S_JI^T)
// ---------------------------------------------------------------------------
__global__ void pack_kernel(const float* __restrict__ Sigma) {
    __shared__ float sA[32][33];
    __shared__ float sB[32][33];
    const int t = blockIdx.x;
    const int b = blockIdx.y;
    int I = 0, rem = t;
    while (rem >= 16 - I) { rem -= 16 - I; ++I; }
    const int J = I + rem;

    const float* S = Sigma + (size_t)b * NDIM * NDIM;
    float* P = g_pack + (size_t)b * INST_STRIDE + (size_t)t * TILE_ELEMS;
    const int tx = threadIdx.x, ty = threadIdx.y;
    const int tid = ty * 32 + tx;

    #pragma unroll
    for (int r = ty; r < 32; r += 8) {
        sA[r][tx] = S[(size_t)(I * 32 + r) * NDIM + J * 32 + tx];
        sB[r][tx] = S[(size_t)(J * 32 + r) * NDIM + I * 32 + tx];
    }
    __syncthreads();

    #pragma unroll
    for (int q = 0; q < 4; ++q) {
        const int addr = tid + (q << 8);
        const int k = addr >> 7;
        const int c = (addr >> 2) & 31;
        const int j = addr & 3;
        const int r = (k << 2) + j;
        P[addr] = 0.5f * (sA[r][c] + sB[c][r]);   // T[r][c]
    }
}

// ---------------------------------------------------------------------------
// warp-local reductions (uniform result on all lanes)
// ---------------------------------------------------------------------------
__device__ __forceinline__ float warp_sum(float v) {
    #pragma unroll
    for (int o = 16; o; o >>= 1) v += __shfl_xor_sync(0xffffffffu, v, o);
    return v;
}
__device__ __forceinline__ float warp_max(float v) {
    #pragma unroll
    for (int o = 16; o; o >>= 1) v = fmaxf(v, __shfl_xor_sync(0xffffffffu, v, o));
    return v;
}

// block reductions for the power-iteration phase
__device__ __forceinline__ float block_sum(float v, volatile float* red,
                                           int lane, int wid) {
    v = warp_sum(v);
    __syncthreads();
    if (lane == 0) red[wid] = v;
    __syncthreads();
    float x = (lane < NWARPS) ? red[lane] : 0.0f;
    return warp_sum(x);
}

// ---------------------------------------------------------------------------
// Tile prefetch into registers (addresses independent of y -> can be issued
// before the scalar-phase barrier to hide L2 latency)
// ---------------------------------------------------------------------------
__device__ __forceinline__ void load_tile(const float* __restrict__ P, int t,
                                          int lane, float4 cur[8]) {
    const float4* PT4 = (const float4*)(P + t * TILE_ELEMS);
    #pragma unroll
    for (int k = 0; k < 8; ++k) cur[k] = PT4[(k << 5) + lane];
}

// ---------------------------------------------------------------------------
// Symmetric matvec, staged two-pass per tile, register double-buffered.
// cur[] must hold tile 'wid' on entry; returns (Ssym*y)[tid].
// ---------------------------------------------------------------------------
__device__ __forceinline__ float matvec_sym(const float* __restrict__ P,
                                            const float* __restrict__ sy,
                                            float* __restrict__ accAll,
                                            float* __restrict__ stageAll,
                                            const int* __restrict__ tI,
                                            const int* __restrict__ tJ,
                                            int tid, int lane, int wid,
                                            float4 cur[8]) {
    float* acc = accAll + (wid << 9);
    {
        const float4 z = make_float4(0.f, 0.f, 0.f, 0.f);
        float4* a4 = (float4*)acc;
        a4[lane] = z; a4[lane + 32] = z; a4[lane + 64] = z; a4[lane + 96] = z;
    }
    float* stg = stageAll + wid * 1152;

    for (int t = wid; t < NTILES; t += NWARPS) {
        float4 nxt[8];
        const int tn = t + NWARPS;
        if (tn < NTILES) load_tile(P, tn, lane, nxt);

        const int I = tI[t], J = tJ[t];
        const float4* yI4 = (const float4*)(sy + (I << 5));
        float a0 = 0.f, a1 = 0.f;
        if (I == J) {
            #pragma unroll
            for (int k = 0; k < 8; ++k) {
                const float4 e  = cur[k];
                const float4 yb = yI4[k];
                a0 = fmaf(e.x, yb.x, a0); a1 = fmaf(e.y, yb.y, a1);
                a0 = fmaf(e.z, yb.z, a0); a1 = fmaf(e.w, yb.w, a1);
            }
            acc[(J << 5) + lane] += a0 + a1;
        } else {
            #pragma unroll
            for (int k = 0; k < 8; ++k) {
                const float4 e  = cur[k];
                const float4 yb = yI4[k];
                a0 = fmaf(e.x, yb.x, a0); a1 = fmaf(e.y, yb.y, a1);
                a0 = fmaf(e.z, yb.z, a0); a1 = fmaf(e.w, yb.w, a1);
                stg[((k << 2) + 0) * 36 + lane] = e.x;   // conflict-free
                stg[((k << 2) + 1) * 36 + lane] = e.y;
                stg[((k << 2) + 2) * 36 + lane] = e.z;
                stg[((k << 2) + 3) * 36 + lane] = e.w;
            }
            acc[(J << 5) + lane] += a0 + a1;
            __syncwarp();
            const float4* yJ4 = (const float4*)(sy + (J << 5));
            float b0 = 0.f, b1 = 0.f;
            #pragma unroll
            for (int m = 0; m < 8; ++m) {
                const float4 s  = *(const float4*)(stg + lane * 36 + (m << 2));
                const float4 yb = yJ4[m];
                b0 = fmaf(s.x, yb.x, b0); b1 = fmaf(s.y, yb.y, b1);
                b0 = fmaf(s.z, yb.z, b0); b1 = fmaf(s.w, yb.w, b1);
            }
            acc[(I << 5) + lane] += b0 + b1;
            __syncwarp();
        }
        #pragma unroll
        for (int k = 0; k < 8; ++k) cur[k] = nxt[k];   // dead if tn>=NTILES
    }
    __syncthreads();
    // cross-warp tree sum (16 partials)
    float s0 = 0.f, s1 = 0.f, s2 = 0.f, s3 = 0.f;
    #pragma unroll
    for (int w = 0; w < 4; ++w) {
        s0 += accAll[((4 * w + 0) << 9) + tid];
        s1 += accAll[((4 * w + 1) << 9) + tid];
        s2 += accAll[((4 * w + 2) << 9) + tid];
        s3 += accAll[((4 * w + 3) << 9) + tid];
    }
    return (s0 + s1) + (s2 + s3);
}

// ---------------------------------------------------------------------------
// Kernel 2: per-instance solver. grid=128 CTAs, block=512 threads.
// ---------------------------------------------------------------------------
__global__ void __launch_bounds__(NTHREADS, 1)
qp_solver_kernel(const float* __restrict__ mu_g, float* __restrict__ out) {
    extern __shared__ float dsm[];
    float* accAll   = dsm + ACC_OFF;
    float* stageAll = dsm + STAGE_OFF;
    float* sy       = dsm + SY_OFF;
    float* sv       = dsm + SV_OFF;
    float* sw       = dsm + SW_OFF;
    __shared__ float red[NWARPS];
    __shared__ int   sh_tI[NTILES], sh_tJ[NTILES];
    __shared__ int   sflag;

    const int b    = blockIdx.x;
    const int tid  = threadIdx.x;
    const int lane = tid & 31;
    const int wid  = tid >> 5;
    const float* P = g_pack + (size_t)b * INST_STRIDE;
    const float invN = 1.0f / (float)NDIM;

    if (tid < NTILES) {
        int I = 0, rem = tid;
        while (rem >= 16 - I) { rem -= 16 - I; ++I; }
        sh_tI[tid] = I;
        sh_tJ[tid] = I + rem;
    }
    if (tid == 0) sflag = 0;
    const float rmu = mu_g[(size_t)b * NDIM + tid];
    sy[tid] = invN;
    __syncthreads();

    float4 cur[8];

    // ---- power iteration (step is answer-independent; 5% margin below) ----
    float ry = invN;
    for (int it = 0; it < POWER_ITERS; ++it) {
        load_tile(P, wid, lane, cur);
        const float gi = matvec_sym(P, sy, accAll, stageAll, sh_tI, sh_tJ,
                                    tid, lane, wid, cur);
        const float ss = block_sum(gi * gi, red, lane, wid);
        const float inv = 1.0f / (sqrtf(ss) + 1e-12f);
        ry = gi * inv;
        sy[tid] = ry;                         // safe: block_sum barriers passed
        __syncthreads();
    }
    load_tile(P, wid, lane, cur);
    const float gi0  = matvec_sym(P, sy, accAll, stageAll, sh_tI, sh_tJ,
                                  tid, lane, wid, cur);
    const float lmax = block_sum(ry * gi0, red, lane, wid);
    const float step = 1.0f / (2.0f * lmax * 1.05f + 1e-8f);

    // ---- FISTA with adaptive restart; scalar phase owned by warp 0 ----
    sy[tid] = invN;
    sw[tid] = invN;
    __syncthreads();
    load_tile(P, wid, lane, cur);
    float t_mom = 1.0f;                       // meaningful in warp 0 only

    for (int it = 0; it < N_ITERS; ++it) {
        const float gi = matvec_sym(P, sy, accAll, stageAll, sh_tI, sh_tJ,
                                    tid, lane, wid, cur);
        const float v = sy[tid] - step * (2.0f * gi - rmu);
        sv[tid] = v;
        load_tile(P, wid, lane, cur);         // prefetch next matvec's 1st tile
        __syncthreads();                      // (B) sv ready

        if (wid == 0) {
            float vv[16];
            #pragma unroll
            for (int j = 0; j < 16; ++j) vv[j] = sv[(j << 5) + lane];

            // simplex projection: Michelot fixed point (== sort-based theta)
            float s = 0.f;
            #pragma unroll
            for (int j = 0; j < 16; ++j) s += vv[j];
            s = warp_sum(s);
            float theta = (s - 1.0f) * invN;
            #pragma unroll 1
            for (int pit = 0; pit < 40; ++pit) {
                float sa = 0.f, sc = 0.f;
                #pragma unroll
                for (int j = 0; j < 16; ++j) {
                    if (vv[j] > theta) { sa += vv[j]; sc += 1.0f; }
                }
                sa = warp_sum(sa); sc = warp_sum(sc);
                const float tn = (sa - 1.0f) / sc;
                if (tn == theta) break;       // uniform across warp
                theta = tn;
            }

            // restart test + convergence
            float mx = 0.f, rdot = 0.f;
            #pragma unroll
            for (int j = 0; j < 16; ++j) {
                const float wo  = sw[(j << 5) + lane];
                const float yo  = sy[(j << 5) + lane];
                const float wnj = fmaxf(vv[j] - theta, 0.0f);
                mx   = fmaxf(mx, fabsf(wnj - wo));
                rdot += (yo - wnj) * (wnj - wo);
            }
            mx = warp_max(mx); rdot = warp_sum(rdot);

            float coef;
            if (rdot > 0.0f) { t_mom = 1.0f; coef = 0.0f; }
            else {
                const float tn = 0.5f * (1.0f + sqrtf(1.0f + 4.0f * t_mom * t_mom));
                coef = (t_mom - 1.0f) / tn;
                t_mom = tn;
            }
            #pragma unroll
            for (int j = 0; j < 16; ++j) {
                const float wo  = sw[(j << 5) + lane];
                const float wnj = fmaxf(vv[j] - theta, 0.0f);
                sw[(j << 5) + lane] = wnj;
                sy[(j << 5) + lane] = wnj + coef * (wnj - wo);
            }
            if (lane == 0) sflag = (mx < 1e-6f) ? 1 : 0;
        }
        __syncthreads();                      // (C) sy/sw/sflag ready
        if (sflag) break;                     // uniform
    }

    out[(size_t)b * NDIM + tid] = sw[tid];
}

// ---------------------------------------------------------------------------
extern "C" void kernel_launch(void* const* d_in, const int* in_sizes, int n_in,
                              void* d_out, int out_size) {
    const float* mu    = (const float*)d_in[0];   // [128, 512]
    const float* Sigma = (const float*)d_in[1];   // [128, 512, 512]
    float* out = (float*)d_out;                   // [128, 512]

    cudaFuncSetAttribute(qp_solver_kernel,
                         cudaFuncAttributeMaxDynamicSharedMemorySize, DSM_BYTES);

    dim3 gs(NTILES, BATCH);
    dim3 bs(32, 8);
    pack_kernel<<<gs, bs>>>(Sigma);
    qp_solver_kernel<<<BATCH, NTHREADS, DSM_BYTES>>>(mu, out);
}